// round 1
// baseline (speedup 1.0000x reference)
#include <cuda_runtime.h>

#define NMAX 32768
#define EMAX 524288
#define EMB  128

// ---------------- scratch (static __device__ globals; no allocation) ----------------
__device__ float g_U [NMAX * EMB];
__device__ float g_H0[NMAX * EMB];
__device__ float g_H1[NMAX * EMB];
__device__ float g_BB[NMAX * EMB];
__device__ float g_inv[NMAX];
__device__ int   g_deg[NMAX];
__device__ int   g_cur[NMAX];
__device__ int   g_rs [NMAX + 1];
__device__ int   g_csr[EMAX];
__device__ float g_G  [64 * EMB];

// ---------------- CSR build ----------------
__global__ void k_zero(int n) {
    int i = blockIdx.x * blockDim.x + threadIdx.x;
    if (i < n) { g_deg[i] = 0; g_cur[i] = 0; }
}

__global__ void k_count(const int* __restrict__ ei, int E) {
    int e = blockIdx.x * blockDim.x + threadIdx.x;
    if (e < E) atomicAdd(&g_deg[ei[E + e]], 1);
}

__global__ void k_scan(int N) {
    __shared__ int sums[1024];
    int tid = threadIdx.x;
    int per = N >> 10;              // N/1024 contiguous nodes per thread
    int base = tid * per;
    int s = 0;
    for (int i = 0; i < per; i++) s += g_deg[base + i];
    sums[tid] = s;
    __syncthreads();
    for (int off = 1; off < 1024; off <<= 1) {
        int v = (tid >= off) ? sums[tid - off] : 0;
        __syncthreads();
        sums[tid] += v;
        __syncthreads();
    }
    int run = (tid == 0) ? 0 : sums[tid - 1];
    for (int i = 0; i < per; i++) { g_rs[base + i] = run; run += g_deg[base + i]; }
    if (tid == 1023) g_rs[N] = run;
}

__global__ void k_inv(int N) {
    int i = blockIdx.x * blockDim.x + threadIdx.x;
    if (i < N) g_inv[i] = rsqrtf((float)(g_deg[i] + 1));   // +1 for self loop
}

__global__ void k_fill(const int* __restrict__ ei, int E) {
    int e = blockIdx.x * blockDim.x + threadIdx.x;
    if (e < E) {
        int d = ei[E + e];
        int pos = g_rs[d] + atomicAdd(&g_cur[d], 1);
        g_csr[pos] = ei[e];
    }
}

// ---------------- tiled fp32 GEMM: Y[N,128] = X[N,K] @ W[K,128] (+epilogue) ---------
// MODE 0: Y = inv[row] * acc       (GCN pre-scale)
// MODE 1: Y = relu(acc + bias[col])(node-head hidden)
// MODE 2: Y = acc                  (edge-head A / Bm)
template <int K, int MODE>
__global__ void __launch_bounds__(256, 2)
k_gemm(const float* __restrict__ X, const float* __restrict__ W,
       const float* __restrict__ P, float* __restrict__ Y) {
    const int BM = 128, BK = 16;
    __shared__ float As[BK][BM + 4];   // transposed X tile, padded
    __shared__ float Bs[BK][BM];

    int tid  = threadIdx.x;
    int row0 = blockIdx.x * BM;
    int trow = (tid >> 4) << 3;   // (tid/16)*8
    int tcol = (tid & 15) << 3;   // (tid%16)*8

    float acc[8][8];
#pragma unroll
    for (int i = 0; i < 8; i++)
#pragma unroll
        for (int j = 0; j < 8; j++) acc[i][j] = 0.f;

    const float* Xb = X + (size_t)row0 * K;
    for (int k0 = 0; k0 < K; k0 += BK) {
#pragma unroll
        for (int i = 0; i < 2; i++) {                 // load As (128x16), transpose
            int idx = tid + i * 256;                  // 0..511
            int r = idx >> 2;
            int c = (idx & 3) << 2;
            float4 v = *(const float4*)(Xb + (size_t)r * K + k0 + c);
            As[c + 0][r] = v.x; As[c + 1][r] = v.y;
            As[c + 2][r] = v.z; As[c + 3][r] = v.w;
        }
#pragma unroll
        for (int i = 0; i < 2; i++) {                 // load Bs (16x128)
            int idx = tid + i * 256;
            int r = idx >> 5;
            int c = (idx & 31) << 2;
            *(float4*)&Bs[r][c] = *(const float4*)(W + (size_t)(k0 + r) * 128 + c);
        }
        __syncthreads();
#pragma unroll
        for (int k = 0; k < BK; k++) {
            float a[8], b[8];
            *(float4*)(a)     = *(const float4*)&As[k][trow];
            *(float4*)(a + 4) = *(const float4*)&As[k][trow + 4];
            *(float4*)(b)     = *(const float4*)&Bs[k][tcol];
            *(float4*)(b + 4) = *(const float4*)&Bs[k][tcol + 4];
#pragma unroll
            for (int i = 0; i < 8; i++)
#pragma unroll
                for (int j = 0; j < 8; j++) acc[i][j] = fmaf(a[i], b[j], acc[i][j]);
        }
        __syncthreads();
    }

#pragma unroll
    for (int i = 0; i < 8; i++) {
        int r = row0 + trow + i;
        float s = (MODE == 0) ? g_inv[r] : 1.f;
#pragma unroll
        for (int j = 0; j < 8; j += 4) {
            float4 v = make_float4(acc[i][j], acc[i][j + 1], acc[i][j + 2], acc[i][j + 3]);
            if (MODE == 0) { v.x *= s; v.y *= s; v.z *= s; v.w *= s; }
            if (MODE == 1) {
                float4 b = *(const float4*)(P + tcol + j);
                v.x = fmaxf(v.x + b.x, 0.f); v.y = fmaxf(v.y + b.y, 0.f);
                v.z = fmaxf(v.z + b.z, 0.f); v.w = fmaxf(v.w + b.w, 0.f);
            }
            *(float4*)(Y + (size_t)r * 128 + tcol + j) = v;
        }
    }
}

// ---------------- GCN aggregation: warp-per-node CSR gather + relu ----------------
__global__ void k_gather(const float* __restrict__ U, const float* __restrict__ bias,
                         float* __restrict__ H, int N) {
    int w    = (blockIdx.x * blockDim.x + threadIdx.x) >> 5;
    int lane = threadIdx.x & 31;
    if (w >= N) return;
    const float4* Ub = (const float4*)U;
    float4 acc  = Ub[w * 32 + lane];                 // self-loop term (inv folded into u)
    float4 acc2 = make_float4(0.f, 0.f, 0.f, 0.f);
    int s = g_rs[w], e = g_rs[w + 1];
    int j = s;
    for (; j + 1 < e; j += 2) {
        int s0 = g_csr[j], s1 = g_csr[j + 1];
        float4 v0 = Ub[s0 * 32 + lane];
        float4 v1 = Ub[s1 * 32 + lane];
        acc.x  += v0.x; acc.y  += v0.y; acc.z  += v0.z; acc.w  += v0.w;
        acc2.x += v1.x; acc2.y += v1.y; acc2.z += v1.z; acc2.w += v1.w;
    }
    if (j < e) {
        float4 v0 = Ub[g_csr[j] * 32 + lane];
        acc.x += v0.x; acc.y += v0.y; acc.z += v0.z; acc.w += v0.w;
    }
    acc.x += acc2.x; acc.y += acc2.y; acc.z += acc2.z; acc.w += acc2.w;
    float iv = g_inv[w];
    float4 b = ((const float4*)bias)[lane];
    float4 o;
    o.x = fmaxf(fmaf(acc.x, iv, b.x), 0.f);
    o.y = fmaxf(fmaf(acc.y, iv, b.y), 0.f);
    o.z = fmaxf(fmaf(acc.z, iv, b.z), 0.f);
    o.w = fmaxf(fmaf(acc.w, iv, b.w), 0.f);
    ((float4*)H)[w * 32 + lane] = o;
}

// ---------------- node head final: warp-per-node t @ wn2 + bn2 -> logits ---------
__global__ void k_node(const float* __restrict__ T, const float* __restrict__ wn2,
                       const float* __restrict__ bn2, float* __restrict__ out,
                       int N, int MA) {
    int w    = (blockIdx.x * blockDim.x + threadIdx.x) >> 5;
    int lane = threadIdx.x & 31;
    if (w >= N) return;
    float4 t = ((const float4*)T)[w * 32 + lane];
    const float4* W4 = (const float4*)wn2;          // row k of wn2 is one float4
    float4 r0 = W4[4 * lane + 0], r1 = W4[4 * lane + 1];
    float4 r2 = W4[4 * lane + 2], r3 = W4[4 * lane + 3];
    float p0 = t.x * r0.x + t.y * r1.x + t.z * r2.x + t.w * r3.x;
    float p1 = t.x * r0.y + t.y * r1.y + t.z * r2.y + t.w * r3.y;
    float p2 = t.x * r0.z + t.y * r1.z + t.z * r2.z + t.w * r3.z;
    float p3 = t.x * r0.w + t.y * r1.w + t.z * r2.w + t.w * r3.w;
#pragma unroll
    for (int off = 16; off; off >>= 1) {
        p0 += __shfl_xor_sync(0xffffffffu, p0, off);
        p1 += __shfl_xor_sync(0xffffffffu, p1, off);
        p2 += __shfl_xor_sync(0xffffffffu, p2, off);
        p3 += __shfl_xor_sync(0xffffffffu, p3, off);
    }
    if (lane == 0) {
        int g = w >> 9, ln = w & 511;
        float* o = out + (size_t)g * MA + ln * 4;
        o[0] = p0 + bn2[0]; o[1] = p1 + bn2[1];
        o[2] = p2 + bn2[2]; o[3] = p3 + bn2[3];
    }
}

// ------- edge head: warp-per-edge relu(A[src]+Bm[dst]+be1) @ we2 + be2 -> logits --
__global__ void k_edge(const float* __restrict__ A, const float* __restrict__ Bm,
                       const int* __restrict__ ei, const float* __restrict__ be1,
                       const float* __restrict__ we2, const float* __restrict__ be2,
                       float* __restrict__ out, int E, int e_per, int MA, int nblk) {
    int w    = (blockIdx.x * blockDim.x + threadIdx.x) >> 5;
    int lane = threadIdx.x & 31;
    if (w >= E) return;
    int src = ei[w], dst = ei[E + w];
    float4 a = ((const float4*)A)[src * 32 + lane];
    float4 b = ((const float4*)Bm)[dst * 32 + lane];
    float4 c = ((const float4*)be1)[lane];
    float t0 = fmaxf(a.x + b.x + c.x, 0.f);
    float t1 = fmaxf(a.y + b.y + c.y, 0.f);
    float t2 = fmaxf(a.z + b.z + c.z, 0.f);
    float t3 = fmaxf(a.w + b.w + c.w, 0.f);
    const float4* W4 = (const float4*)we2;          // float4 i covers rows 2i,2i+1
    float4 w01 = W4[2 * lane], w23 = W4[2 * lane + 1];
    float p0 = t0 * w01.x + t1 * w01.z + t2 * w23.x + t3 * w23.z;
    float p1 = t0 * w01.y + t1 * w01.w + t2 * w23.y + t3 * w23.w;
#pragma unroll
    for (int off = 16; off; off >>= 1) {
        p0 += __shfl_xor_sync(0xffffffffu, p0, off);
        p1 += __shfl_xor_sync(0xffffffffu, p1, off);
    }
    if (lane == 0) {
        int g = w / e_per, le = w - g * e_per;
        float* o = out + (size_t)g * MA + nblk + le * 2;
        o[0] = p0 + be2[0];
        o[1] = p1 + be2[1];
    }
}

// ---------------- value head ----------------
__global__ void k_pool(const float* __restrict__ H, int n_per) {
    int g = blockIdx.x, c = threadIdx.x;
    const float* base = H + (size_t)g * n_per * 128 + c;
    float s = 0.f;
#pragma unroll 8
    for (int r = 0; r < n_per; r++) s += base[(size_t)r * 128];
    g_G[g * 128 + c] = s / (float)n_per;
}

__global__ void k_value(const float* __restrict__ wv1, const float* __restrict__ bv1,
                        const float* __restrict__ wv2, const float* __restrict__ bv2,
                        float* __restrict__ out, int voff) {
    __shared__ float gs[128];
    __shared__ float red[128];
    int g = blockIdx.x, t = threadIdx.x;
    gs[t] = g_G[g * 128 + t];
    __syncthreads();
    float acc = bv1[t];
#pragma unroll
    for (int k = 0; k < 128; k++) acc = fmaf(gs[k], wv1[k * 128 + t], acc);
    acc = fmaxf(acc, 0.f) * wv2[t];
    red[t] = acc;
    __syncthreads();
    for (int off = 64; off; off >>= 1) {
        if (t < off) red[t] += red[t + off];
        __syncthreads();
    }
    if (t == 0) out[voff + g] = red[0] + bv2[0];
}

// ---------------- launch ----------------
extern "C" void kernel_launch(void* const* d_in, const int* in_sizes, int n_in,
                              void* d_out, int out_size) {
    const float* x  = (const float*)d_in[0];
    const int*   ei = (const int*)d_in[1];     // [2,E] int32 (JAX default, x64 off)
    int N = in_sizes[0] / 64;
    int E = in_sizes[1] / 2;

    int wb = n_in - 18;                        // 18 weight/bias arrays at the tail
    const float* w_g1 = (const float*)d_in[wb + 0];
    const float* b_g1 = (const float*)d_in[wb + 1];
    const float* w_g2 = (const float*)d_in[wb + 2];
    const float* b_g2 = (const float*)d_in[wb + 3];
    const float* w_g3 = (const float*)d_in[wb + 4];
    const float* b_g3 = (const float*)d_in[wb + 5];
    const float* wn1  = (const float*)d_in[wb + 6];
    const float* bn1  = (const float*)d_in[wb + 7];
    const float* wn2  = (const float*)d_in[wb + 8];
    const float* bn2  = (const float*)d_in[wb + 9];
    const float* we1  = (const float*)d_in[wb + 10];
    const float* be1  = (const float*)d_in[wb + 11];
    const float* we2  = (const float*)d_in[wb + 12];
    const float* be2  = (const float*)d_in[wb + 13];
    const float* wv1  = (const float*)d_in[wb + 14];
    const float* bv1  = (const float*)d_in[wb + 15];
    const float* wv2  = (const float*)d_in[wb + 16];
    const float* bv2  = (const float*)d_in[wb + 17];

    const int n_per = 512;
    int B     = N / n_per;
    int e_per = E / B;
    int MA    = n_per * 4 + e_per * 2;
    int voff  = out_size - B;
    float* out = (float*)d_out;

    float *U, *H0, *H1, *BB;
    cudaGetSymbolAddress((void**)&U,  g_U);
    cudaGetSymbolAddress((void**)&H0, g_H0);
    cudaGetSymbolAddress((void**)&H1, g_H1);
    cudaGetSymbolAddress((void**)&BB, g_BB);

    // CSR over dst (topology fixed per call; rebuilt deterministically in-graph)
    k_zero <<<(N + 255) / 256, 256>>>(N);
    k_count<<<(E + 255) / 256, 256>>>(ei, E);
    k_scan <<<1, 1024>>>(N);
    k_inv  <<<(N + 255) / 256, 256>>>(N);
    k_fill <<<(E + 255) / 256, 256>>>(ei, E);

    int gg = N / 128;                          // gemm grid
    int gw = (N * 32 + 255) / 256;             // warp-per-node grid

    // GCN layer 1 (K=64)
    k_gemm<64, 0><<<gg, 256>>>(x, w_g1, nullptr, U);
    k_gather<<<gw, 256>>>(U, b_g1, H0, N);
    // GCN layer 2
    k_gemm<128, 0><<<gg, 256>>>(H0, w_g2, nullptr, U);
    k_gather<<<gw, 256>>>(U, b_g2, H1, N);
    // GCN layer 3 -> h3 in H0
    k_gemm<128, 0><<<gg, 256>>>(H1, w_g3, nullptr, U);
    k_gather<<<gw, 256>>>(U, b_g3, H0, N);

    // node head: t = relu(h3@wn1+bn1) in H1, then t@wn2+bn2 -> logits
    k_gemm<128, 1><<<gg, 256>>>(H0, wn1, bn1, H1);
    k_node<<<gw, 256>>>(H1, wn2, bn2, out, N, MA);

    // edge head (factored): A = h3@we1_top (in U), Bm = h3@we1_bot (in BB)
    k_gemm<128, 2><<<gg, 256>>>(H0, we1, nullptr, U);
    k_gemm<128, 2><<<gg, 256>>>(H0, we1 + 128 * 128, nullptr, BB);
    k_edge<<<(E * 32 + 255) / 256, 256>>>(U, BB, ei, be1, we2, be2,
                                          out, E, e_per, MA, n_per * 4);

    // value head
    k_pool <<<B, 128>>>(H0, n_per);
    k_value<<<B, 128>>>(wv1, bv1, wv2, bv2, out, voff);
}

// round 4
// speedup vs baseline: 1.1076x; 1.1076x over previous
#include <cuda_runtime.h>
#include <cuda_bf16.h>
#include <cstdint>

#define NMAX 32768
#define EMAX 524288

// ---------------- scratch (static device globals; no allocation) ----------------
__device__ float g_U [NMAX * 128];
__device__ float g_A [NMAX * 128];
__device__ float g_B [NMAX * 128];
__device__ __nv_bfloat16 g_Hhi[NMAX * 128];
__device__ __nv_bfloat16 g_Hlo[NMAX * 128];
__device__ __nv_bfloat16 g_Xhi[NMAX * 64];
__device__ __nv_bfloat16 g_Xlo[NMAX * 64];
__device__ __nv_bfloat16 g_Whi[6 * 128 * 128];
__device__ __nv_bfloat16 g_Wlo[6 * 128 * 128];
__device__ float g_inv[NMAX];
__device__ int   g_deg[NMAX];
__device__ int   g_cur[NMAX];
__device__ int   g_rs [NMAX + 1];
__device__ int   g_csr[EMAX];
__device__ float g_G  [64 * 128];

// ---------------- CSR build ----------------
__global__ void k_zero(int n) {
    int i = blockIdx.x * blockDim.x + threadIdx.x;
    if (i < n) { g_deg[i] = 0; g_cur[i] = 0; }
}
__global__ void k_count(const int* __restrict__ ei, int E) {
    int e = blockIdx.x * blockDim.x + threadIdx.x;
    if (e < E) atomicAdd(&g_deg[ei[E + e]], 1);
}
__global__ void k_scan(int N) {
    __shared__ int sums[1024];
    int tid = threadIdx.x;
    int per = N >> 10;
    int base = tid * per;
    int s = 0;
    for (int i = 0; i < per; i++) s += g_deg[base + i];
    sums[tid] = s;
    __syncthreads();
    for (int off = 1; off < 1024; off <<= 1) {
        int v = (tid >= off) ? sums[tid - off] : 0;
        __syncthreads();
        sums[tid] += v;
        __syncthreads();
    }
    int run = (tid == 0) ? 0 : sums[tid - 1];
    for (int i = 0; i < per; i++) {
        int d = g_deg[base + i];
        g_rs[base + i] = run; run += d;
        g_inv[base + i] = rsqrtf((float)(d + 1));
    }
    if (tid == 1023) g_rs[N] = run;
}
__global__ void k_fill(const int* __restrict__ ei, int E) {
    int e = blockIdx.x * blockDim.x + threadIdx.x;
    if (e < E) {
        int d = ei[E + e];
        int pos = g_rs[d] + atomicAdd(&g_cur[d], 1);
        g_csr[pos] = ei[e];
    }
}

// ---------------- conversions ----------------
__global__ void k_convX(const float* __restrict__ x, int n2) {   // n2 = N*64/2
    int i = blockIdx.x * blockDim.x + threadIdx.x;
    if (i >= n2) return;
    float2 v = ((const float2*)x)[i];
    __nv_bfloat16 hx = __float2bfloat16(v.x), hy = __float2bfloat16(v.y);
    __nv_bfloat162 hi; hi.x = hx; hi.y = hy;
    __nv_bfloat162 lo;
    lo.x = __float2bfloat16(v.x - __bfloat162float(hx));
    lo.y = __float2bfloat16(v.y - __bfloat162float(hy));
    ((__nv_bfloat162*)g_Xhi)[i] = hi;
    ((__nv_bfloat162*)g_Xlo)[i] = lo;
}
__global__ void k_convW(const float* w0, const float* w1, const float* w2,
                        const float* w3, const float* w4, const float* w5) {
    const float* srcs[6] = {w0, w1, w2, w3, w4, w5};
    const int Ks[6] = {64, 128, 128, 128, 128, 128};
    int b = blockIdx.x;
    const float* W = srcs[b];
    int K = Ks[b];
    __nv_bfloat16* oh = g_Whi + b * 16384;
    __nv_bfloat16* ol = g_Wlo + b * 16384;
    for (int id = threadIdx.x; id < 128 * K; id += blockDim.x) {
        int n = id / K, k = id % K;
        float v = W[k * 128 + n];                 // transpose: Wt[n,k] = W[k,n]
        __nv_bfloat16 h = __float2bfloat16(v);
        oh[id] = h;
        ol[id] = __float2bfloat16(v - __bfloat162float(h));
    }
}

// ---------------- mma.sync bf16 GEMM: Y[128,128] = X[128,K] @ Wt^T ---------------
// bf16x3 split: D = AhiBhi + AhiBlo + AloBhi  (~fp32 accuracy, fp32 accum)
// Warp tile m32 x n64: warp w -> rows (w&3)*32.., col half (w>>2).
// MODE 0: Y = inv[row]*acc   MODE 1: fused node head -> out   MODE 2: Y = acc
#define MMA16816(c, a, b0, b1)                                             \
    asm volatile("mma.sync.aligned.m16n8k16.row.col.f32.bf16.bf16.f32 "    \
        "{%0,%1,%2,%3}, {%4,%5,%6,%7}, {%8,%9}, {%0,%1,%2,%3};"            \
        : "+f"((c)[0]), "+f"((c)[1]), "+f"((c)[2]), "+f"((c)[3])           \
        : "r"((a)[0]), "r"((a)[1]), "r"((a)[2]), "r"((a)[3]),              \
          "r"(b0), "r"(b1))

template <int K, int MODE>
__global__ void __launch_bounds__(256)
k_gemm_mma(const __nv_bfloat16* __restrict__ Xhi, const __nv_bfloat16* __restrict__ Xlo,
           const __nv_bfloat16* __restrict__ Whi, const __nv_bfloat16* __restrict__ Wlo,
           const float* __restrict__ bias, const float* __restrict__ wn2,
           const float* __restrict__ bn2, float* __restrict__ Y,
           float* __restrict__ out, int MA) {
    constexpr int KP = K + 8;                       // padded row stride (bf16)
    extern __shared__ __nv_bfloat16 sB[];           // [2][128][KP]
    __nv_bfloat16* sBhi = sB;
    __nv_bfloat16* sBlo = sB + 128 * KP;
    __shared__ float slg[2][128][4];                // MODE1 cross-warp logits

    int tid = threadIdx.x, wid = tid >> 5, lane = tid & 31;
    int q = lane & 3, g4 = lane >> 2;
    int m0 = blockIdx.x * 128 + (wid & 3) * 32;
    int nh = wid >> 2;                              // column half 0/1

    // stage weights (hi+lo) into padded shared
    for (int id = tid; id < 128 * (K / 8); id += 256) {
        int n = id / (K / 8), kb = (id % (K / 8)) * 8;
        *(float4*)&sBhi[n * KP + kb] = *(const float4*)(Whi + (size_t)n * K + kb);
        *(float4*)&sBlo[n * KP + kb] = *(const float4*)(Wlo + (size_t)n * K + kb);
    }
    __syncthreads();

    float c[2][8][4] = {};
    for (int kc = 0; kc < K / 16; kc++) {
        int k0 = kc * 16;
        uint32_t ah[2][4], al[2][4];
#pragma unroll
        for (int mh = 0; mh < 2; mh++) {
            size_t base = (size_t)(m0 + mh * 16 + g4) * K + k0 + q * 2;
            ah[mh][0] = *(const uint32_t*)(Xhi + base);
            ah[mh][1] = *(const uint32_t*)(Xhi + base + 8 * K);
            ah[mh][2] = *(const uint32_t*)(Xhi + base + 8);
            ah[mh][3] = *(const uint32_t*)(Xhi + base + 8 * K + 8);
            al[mh][0] = *(const uint32_t*)(Xlo + base);
            al[mh][1] = *(const uint32_t*)(Xlo + base + 8 * K);
            al[mh][2] = *(const uint32_t*)(Xlo + base + 8);
            al[mh][3] = *(const uint32_t*)(Xlo + base + 8 * K + 8);
        }
#pragma unroll
        for (int nc = 0; nc < 8; nc++) {
            int n = nh * 64 + nc * 8 + g4;
            const __nv_bfloat16* pb = &sBhi[n * KP + k0 + q * 2];
            const __nv_bfloat16* pl = &sBlo[n * KP + k0 + q * 2];
            uint32_t bh0 = *(const uint32_t*)pb, bh1 = *(const uint32_t*)(pb + 8);
            uint32_t bl0 = *(const uint32_t*)pl, bl1 = *(const uint32_t*)(pl + 8);
#pragma unroll
            for (int mh = 0; mh < 2; mh++) {
                MMA16816(c[mh][nc], ah[mh], bh0, bh1);
                MMA16816(c[mh][nc], ah[mh], bl0, bl1);
                MMA16816(c[mh][nc], al[mh], bh0, bh1);
            }
        }
    }

    if (MODE == 0 || MODE == 2) {
#pragma unroll
        for (int mh = 0; mh < 2; mh++) {
            int r0 = m0 + mh * 16 + g4;
            float s0 = 1.f, s1 = 1.f;
            if (MODE == 0) { s0 = g_inv[r0]; s1 = g_inv[r0 + 8]; }
#pragma unroll
            for (int nc = 0; nc < 8; nc++) {
                int col = nh * 64 + nc * 8 + q * 2;
                float2 v0 = make_float2(c[mh][nc][0] * s0, c[mh][nc][1] * s0);
                float2 v1 = make_float2(c[mh][nc][2] * s1, c[mh][nc][3] * s1);
                *(float2*)(Y + (size_t)r0 * 128 + col)       = v0;
                *(float2*)(Y + (size_t)(r0 + 8) * 128 + col) = v1;
            }
        }
    } else {
        // fused node head: t = relu(acc + bn1[col]); logits += t * wn2[col][:]
        float lg[4][4] = {};                        // row-offset {0,8,16,24} x action
#pragma unroll
        for (int mh = 0; mh < 2; mh++) {
#pragma unroll
            for (int nc = 0; nc < 8; nc++) {
                int col = nh * 64 + nc * 8 + q * 2;
                float b0 = __ldg(bias + col), b1 = __ldg(bias + col + 1);
                float4 w0 = __ldg((const float4*)wn2 + col);
                float4 w1 = __ldg((const float4*)wn2 + col + 1);
                float t0 = fmaxf(c[mh][nc][0] + b0, 0.f);
                float t1 = fmaxf(c[mh][nc][1] + b1, 0.f);
                float t2 = fmaxf(c[mh][nc][2] + b0, 0.f);
                float t3 = fmaxf(c[mh][nc][3] + b1, 0.f);
                int ra = mh * 2, rb = mh * 2 + 1;
                lg[ra][0] += t0 * w0.x + t1 * w1.x;
                lg[ra][1] += t0 * w0.y + t1 * w1.y;
                lg[ra][2] += t0 * w0.z + t1 * w1.z;
                lg[ra][3] += t0 * w0.w + t1 * w1.w;
                lg[rb][0] += t2 * w0.x + t3 * w1.x;
                lg[rb][1] += t2 * w0.y + t3 * w1.y;
                lg[rb][2] += t2 * w0.z + t3 * w1.z;
                lg[rb][3] += t2 * w0.w + t3 * w1.w;
            }
        }
#pragma unroll
        for (int i = 0; i < 4; i++)
#pragma unroll
            for (int a = 0; a < 4; a++) {
                lg[i][a] += __shfl_xor_sync(0xffffffffu, lg[i][a], 1);
                lg[i][a] += __shfl_xor_sync(0xffffffffu, lg[i][a], 2);
            }
        if (q == 0) {
            int lr0 = (wid & 3) * 32 + g4;          // local row in [0,128)
#pragma unroll
            for (int i = 0; i < 4; i++) {
                int lr = lr0 + ((i & 1) ? 8 : 0) + ((i >> 1) ? 16 : 0);
#pragma unroll
                for (int a = 0; a < 4; a++) slg[nh][lr][a] = lg[i][a];
            }
        }
        __syncthreads();
        for (int id = tid; id < 512; id += 256) {
            int lr = id >> 2, a = id & 3;
            int R = blockIdx.x * 128 + lr;
            int g = R >> 9, ln = R & 511;
            out[(size_t)g * MA + ln * 4 + a] =
                slg[0][lr][a] + slg[1][lr][a] + __ldg(bn2 + a);
        }
    }
}

// ---------------- GCN aggregation: warp-per-node CSR gather + relu ----------------
// output written as bf16 hi/lo split (consumed by next mma gemm / pool)
__global__ void k_gather(const float* __restrict__ U, const float* __restrict__ bias,
                         __nv_bfloat16* __restrict__ Hhi, __nv_bfloat16* __restrict__ Hlo,
                         int N) {
    int w    = (blockIdx.x * blockDim.x + threadIdx.x) >> 5;
    int lane = threadIdx.x & 31;
    if (w >= N) return;
    const float4* Ub = (const float4*)U;
    float4 acc  = Ub[w * 32 + lane];
    float4 acc2 = make_float4(0.f, 0.f, 0.f, 0.f);
    int s = g_rs[w], e = g_rs[w + 1];
    int j = s;
    for (; j + 1 < e; j += 2) {
        int s0 = g_csr[j], s1 = g_csr[j + 1];
        float4 v0 = Ub[s0 * 32 + lane];
        float4 v1 = Ub[s1 * 32 + lane];
        acc.x  += v0.x; acc.y  += v0.y; acc.z  += v0.z; acc.w  += v0.w;
        acc2.x += v1.x; acc2.y += v1.y; acc2.z += v1.z; acc2.w += v1.w;
    }
    if (j < e) {
        float4 v0 = Ub[g_csr[j] * 32 + lane];
        acc.x += v0.x; acc.y += v0.y; acc.z += v0.z; acc.w += v0.w;
    }
    acc.x += acc2.x; acc.y += acc2.y; acc.z += acc2.z; acc.w += acc2.w;
    float iv = g_inv[w];
    float4 b = ((const float4*)bias)[lane];
    float ox = fmaxf(fmaf(acc.x, iv, b.x), 0.f);
    float oy = fmaxf(fmaf(acc.y, iv, b.y), 0.f);
    float oz = fmaxf(fmaf(acc.z, iv, b.z), 0.f);
    float ow = fmaxf(fmaf(acc.w, iv, b.w), 0.f);
    __nv_bfloat16 hx = __float2bfloat16(ox), hy = __float2bfloat16(oy);
    __nv_bfloat16 hz = __float2bfloat16(oz), hw = __float2bfloat16(ow);
    __nv_bfloat162 h01; h01.x = hx; h01.y = hy;
    __nv_bfloat162 h23; h23.x = hz; h23.y = hw;
    __nv_bfloat162 l01, l23;
    l01.x = __float2bfloat16(ox - __bfloat162float(hx));
    l01.y = __float2bfloat16(oy - __bfloat162float(hy));
    l23.x = __float2bfloat16(oz - __bfloat162float(hz));
    l23.y = __float2bfloat16(ow - __bfloat162float(hw));
    ((__nv_bfloat162*)Hhi)[w * 64 + lane * 2]     = h01;
    ((__nv_bfloat162*)Hhi)[w * 64 + lane * 2 + 1] = h23;
    ((__nv_bfloat162*)Hlo)[w * 64 + lane * 2]     = l01;
    ((__nv_bfloat162*)Hlo)[w * 64 + lane * 2 + 1] = l23;
}

// ------- edge head: warp-per-edge relu(A[src]+Bm[dst]+be1) @ we2 + be2 ------------
__global__ void k_edge(const float* __restrict__ A, const float* __restrict__ Bm,
                       const int* __restrict__ ei, const float* __restrict__ be1,
                       const float* __restrict__ we2, const float* __restrict__ be2,
                       float* __restrict__ out, int E, int e_per, int MA, int nblk) {
    __shared__ float sred[16];
    int w    = (blockIdx.x * blockDim.x + threadIdx.x) >> 5;
    int wid  = threadIdx.x >> 5;
    int lane = threadIdx.x & 31;
    int src = ei[w], dst = ei[E + w];
    float4 a = ((const float4*)A)[src * 32 + lane];
    float4 b = ((const float4*)Bm)[dst * 32 + lane];
    float4 c = ((const float4*)be1)[lane];
    float t0 = fmaxf(a.x + b.x + c.x, 0.f);
    float t1 = fmaxf(a.y + b.y + c.y, 0.f);
    float t2 = fmaxf(a.z + b.z + c.z, 0.f);
    float t3 = fmaxf(a.w + b.w + c.w, 0.f);
    const float4* W4 = (const float4*)we2;
    float4 w01 = W4[2 * lane], w23 = W4[2 * lane + 1];
    float p0 = t0 * w01.x + t1 * w01.z + t2 * w23.x + t3 * w23.z;
    float p1 = t0 * w01.y + t1 * w01.w + t2 * w23.y + t3 * w23.w;
#pragma unroll
    for (int off = 16; off; off >>= 1) {
        p0 += __shfl_xor_sync(0xffffffffu, p0, off);
        p1 += __shfl_xor_sync(0xffffffffu, p1, off);
    }
    if (lane == 0) {
        sred[wid * 2]     = p0 + be2[0];
        sred[wid * 2 + 1] = p1 + be2[1];
    }
    __syncthreads();
    if (threadIdx.x < 16) {
        int e0 = blockIdx.x * 8;
        int g = e0 / e_per;
        int base = g * MA + nblk + (e0 - g * e_per) * 2;
        out[base + threadIdx.x] = sred[threadIdx.x];
    }
}

// ---------------- value head ----------------
__global__ void k_pool(int n_per) {
    int g = blockIdx.x, c = threadIdx.x;
    const __nv_bfloat16* ph = g_Hhi + (size_t)g * n_per * 128 + c;
    const __nv_bfloat16* pl = g_Hlo + (size_t)g * n_per * 128 + c;
    float s = 0.f;
#pragma unroll 8
    for (int r = 0; r < n_per; r++)
        s += __bfloat162float(ph[(size_t)r * 128]) + __bfloat162float(pl[(size_t)r * 128]);
    g_G[g * 128 + c] = s / (float)n_per;
}

__global__ void k_value(const float* __restrict__ wv1, const float* __restrict__ bv1,
                        const float* __restrict__ wv2, const float* __restrict__ bv2,
                        float* __restrict__ out, int voff) {
    __shared__ float gs[128];
    __shared__ float red[128];
    int g = blockIdx.x, t = threadIdx.x;
    gs[t] = g_G[g * 128 + t];
    __syncthreads();
    float acc = bv1[t];
#pragma unroll
    for (int k = 0; k < 128; k++) acc = fmaf(gs[k], wv1[k * 128 + t], acc);
    acc = fmaxf(acc, 0.f) * wv2[t];
    red[t] = acc;
    __syncthreads();
    for (int off = 64; off; off >>= 1) {
        if (t < off) red[t] += red[t + off];
        __syncthreads();
    }
    if (t == 0) out[voff + g] = red[0] + bv2[0];
}

// ---------------- launch ----------------
extern "C" void kernel_launch(void* const* d_in, const int* in_sizes, int n_in,
                              void* d_out, int out_size) {
    const float* x  = (const float*)d_in[0];
    const int*   ei = (const int*)d_in[1];
    int N = in_sizes[0] / 64;
    int E = in_sizes[1] / 2;

    int wb = n_in - 18;
    const float* w_g1 = (const float*)d_in[wb + 0];
    const float* b_g1 = (const float*)d_in[wb + 1];
    const float* w_g2 = (const float*)d_in[wb + 2];
    const float* b_g2 = (const float*)d_in[wb + 3];
    const float* w_g3 = (const float*)d_in[wb + 4];
    const float* b_g3 = (const float*)d_in[wb + 5];
    const float* wn1  = (const float*)d_in[wb + 6];
    const float* bn1  = (const float*)d_in[wb + 7];
    const float* wn2  = (const float*)d_in[wb + 8];
    const float* bn2  = (const float*)d_in[wb + 9];
    const float* we1  = (const float*)d_in[wb + 10];
    const float* be1  = (const float*)d_in[wb + 11];
    const float* we2  = (const float*)d_in[wb + 12];
    const float* be2  = (const float*)d_in[wb + 13];
    const float* wv1  = (const float*)d_in[wb + 14];
    const float* bv1  = (const float*)d_in[wb + 15];
    const float* wv2  = (const float*)d_in[wb + 16];
    const float* bv2  = (const float*)d_in[wb + 17];

    const int n_per = 512;
    int B     = N / n_per;
    int e_per = E / B;
    int MA    = n_per * 4 + e_per * 2;
    int voff  = out_size - B;
    float* out = (float*)d_out;

    float *U, *A, *Bm;
    __nv_bfloat16 *Hhi, *Hlo, *Xhi, *Xlo, *Whi, *Wlo;
    cudaGetSymbolAddress((void**)&U,   g_U);
    cudaGetSymbolAddress((void**)&A,   g_A);
    cudaGetSymbolAddress((void**)&Bm,  g_B);
    cudaGetSymbolAddress((void**)&Hhi, g_Hhi);
    cudaGetSymbolAddress((void**)&Hlo, g_Hlo);
    cudaGetSymbolAddress((void**)&Xhi, g_Xhi);
    cudaGetSymbolAddress((void**)&Xlo, g_Xlo);
    cudaGetSymbolAddress((void**)&Whi, g_Whi);
    cudaGetSymbolAddress((void**)&Wlo, g_Wlo);

    const int SM64  = 2 * 128 * (64 + 8)  * 2;     // 36,864 B
    const int SM128 = 2 * 128 * (128 + 8) * 2;     // 69,632 B
    cudaFuncSetAttribute(k_gemm_mma<64, 0>,  cudaFuncAttributeMaxDynamicSharedMemorySize, SM64);
    cudaFuncSetAttribute(k_gemm_mma<128, 0>, cudaFuncAttributeMaxDynamicSharedMemorySize, SM128);
    cudaFuncSetAttribute(k_gemm_mma<128, 1>, cudaFuncAttributeMaxDynamicSharedMemorySize, SM128);
    cudaFuncSetAttribute(k_gemm_mma<128, 2>, cudaFuncAttributeMaxDynamicSharedMemorySize, SM128);

    // CSR build
    k_zero <<<(N + 255) / 256, 256>>>(N);
    k_count<<<(E + 255) / 256, 256>>>(ei, E);
    k_scan <<<1, 1024>>>(N);
    k_fill <<<(E + 255) / 256, 256>>>(ei, E);

    // conversions
    k_convX<<<(N * 32 + 255) / 256, 256>>>(x, N * 32);
    k_convW<<<6, 256>>>(w_g1, w_g2, w_g3, wn1, we1, we1 + 128 * 128);

    int gg = N / 128;
    int gw = (N * 32 + 255) / 256;

    // GCN layer 1 (K=64)
    k_gemm_mma<64, 0><<<gg, 256, SM64>>>(Xhi, Xlo, Whi + 0 * 16384, Wlo + 0 * 16384,
                                         nullptr, nullptr, nullptr, U, nullptr, 0);
    k_gather<<<gw, 256>>>(U, b_g1, Hhi, Hlo, N);
    // GCN layer 2
    k_gemm_mma<128, 0><<<gg, 256, SM128>>>(Hhi, Hlo, Whi + 1 * 16384, Wlo + 1 * 16384,
                                           nullptr, nullptr, nullptr, U, nullptr, 0);
    k_gather<<<gw, 256>>>(U, b_g2, Hhi, Hlo, N);
    // GCN layer 3
    k_gemm_mma<128, 0><<<gg, 256, SM128>>>(Hhi, Hlo, Whi + 2 * 16384, Wlo + 2 * 16384,
                                           nullptr, nullptr, nullptr, U, nullptr, 0);
    k_gather<<<gw, 256>>>(U, b_g3, Hhi, Hlo, N);

    // node head (fully fused: t = relu(h3@wn1+bn1); logits = t@wn2+bn2 -> out)
    k_gemm_mma<128, 1><<<gg, 256, SM128>>>(Hhi, Hlo, Whi + 3 * 16384, Wlo + 3 * 16384,
                                           bn1, wn2, bn2, nullptr, out, MA);

    // edge head (factored): A = h3@we1_top, Bm = h3@we1_bot
    k_gemm_mma<128, 2><<<gg, 256, SM128>>>(Hhi, Hlo, Whi + 4 * 16384, Wlo + 4 * 16384,
                                           nullptr, nullptr, nullptr, A, nullptr, 0);
    k_gemm_mma<128, 2><<<gg, 256, SM128>>>(Hhi, Hlo, Whi + 5 * 16384, Wlo + 5 * 16384,
                                           nullptr, nullptr, nullptr, Bm, nullptr, 0);
    k_edge<<<E / 8, 256>>>(A, Bm, ei, be1, we2, be2, out, E, e_per, MA, n_per * 4);

    // value head
    k_pool <<<B, 128>>>(n_per);
    k_value<<<B, 128>>>(wv1, bv1, wv2, bv2, out, voff);
}